// round 3
// baseline (speedup 1.0000x reference)
#include <cuda_runtime.h>

#define BB 4
#define HH 256
#define WW 256
#define NN 256

// 13-tap Gaussian (stdev=2) and its derivative filter, normalized exactly as the
// reference (g /= g.sum(); dg = -x/stdev^2 * g), evaluated at x = idx-6.
__constant__ float c_G[13] = {
    0.00221820f, 0.00877313f, 0.02702315f, 0.06482518f, 0.12110938f,
    0.17621311f, 0.19967563f, 0.17621311f, 0.12110938f, 0.06482518f,
    0.02702315f, 0.00877313f, 0.00221820f};
__constant__ float c_DG[13] = {
    0.00332730f, 0.01096641f, 0.02702315f, 0.04861888f, 0.06055469f,
    0.04405328f, 0.00000000f, -0.04405328f, -0.06055469f, -0.04861888f,
    -0.02702315f, -0.01096641f, -0.00332730f};

// Scratch (static __device__ arrays: allocation-free).
__device__ float g_gimg[BB * 2 * HH * WW];  // [b][c][y][x], c=0: y-grad, c=1: x-grad
__device__ float g_gw[BB * HH * WW];        // summed-channel gradient of |pred|
__device__ float g_py[BB * NN], g_px[BB * NN], g_wd[BB * NN];
__device__ double g_part[BB * 64];

// ---------------------------------------------------------------------------
// Stage 1: separable 13x13 conv. One block = one 32x32 output tile.
// ch0 = vconv(hconv(x, g), dg); ch1 = vconv(hconv(x, dg), g); gw = same on |x|, channels summed.
// ---------------------------------------------------------------------------
__global__ __launch_bounds__(256) void conv_kernel(const float* __restrict__ x) {
    __shared__ float s_in[44][48];
    __shared__ float s_hg[44][32];
    __shared__ float s_hd[44][32];
    __shared__ float s_ag[44][32];
    __shared__ float s_ad[44][32];

    const int b = blockIdx.z;
    const int ty0 = blockIdx.y * 32, tx0 = blockIdx.x * 32;
    const float* xb = x + b * HH * WW;
    const int t = threadIdx.x;

    // Load 44x44 input tile with 6-px halo, zero padding ('SAME').
    for (int idx = t; idx < 44 * 44; idx += 256) {
        int iy = idx / 44, ix = idx % 44;
        int gy = ty0 + iy - 6, gx = tx0 + ix - 6;
        float v = 0.0f;
        if ((unsigned)gy < HH && (unsigned)gx < WW) v = xb[gy * WW + gx];
        s_in[iy][ix] = v;
    }
    __syncthreads();

    // Horizontal pass (rows with halo, 32 output columns).
    for (int idx = t; idx < 44 * 32; idx += 256) {
        int iy = idx / 32, ix = idx % 32;
        float hg = 0.f, hd = 0.f, ag = 0.f, ad = 0.f;
#pragma unroll
        for (int l = 0; l < 13; l++) {
            float v = s_in[iy][ix + l];
            float a = fabsf(v);
            hg = fmaf(c_G[l], v, hg);
            hd = fmaf(c_DG[l], v, hd);
            ag = fmaf(c_G[l], a, ag);
            ad = fmaf(c_DG[l], a, ad);
        }
        s_hg[iy][ix] = hg;
        s_hd[iy][ix] = hd;
        s_ag[iy][ix] = ag;
        s_ad[iy][ix] = ad;
    }
    __syncthreads();

    // Vertical pass, 32x32 outputs.
    for (int idx = t; idx < 32 * 32; idx += 256) {
        int iy = idx / 32, ix = idx % 32;
        float c0 = 0.f, c1 = 0.f, w0 = 0.f, w1 = 0.f;
#pragma unroll
        for (int k = 0; k < 13; k++) {
            c0 = fmaf(c_DG[k], s_hg[iy + k][ix], c0);
            c1 = fmaf(c_G[k], s_hd[iy + k][ix], c1);
            w0 = fmaf(c_DG[k], s_ag[iy + k][ix], w0);
            w1 = fmaf(c_G[k], s_ad[iy + k][ix], w1);
        }
        int gy = ty0 + iy, gx = tx0 + ix;
        g_gimg[((b * 2 + 0) * HH + gy) * WW + gx] = 10.0f * c0;  // EXTGRADFAC
        g_gimg[((b * 2 + 1) * HH + gy) * WW + gx] = 10.0f * c1;
        g_gw[(b * HH + gy) * WW + gx] = 10.0f * (w0 + w1);
    }
}

// ---------------------------------------------------------------------------
// Stage 2: snake optimization. One block per batch, one thread per node.
// ---------------------------------------------------------------------------
__device__ __forceinline__ float bilin(const float* __restrict__ img, float y, float x) {
    y = fminf(fmaxf(y, 0.0f), 254.999f);  // H - 1.001
    x = fminf(fmaxf(x, 0.0f), 254.999f);
    float fy = floorf(y), fx = floorf(x);
    int y0 = (int)fy, x0 = (int)fx;
    float ty = y - fy, tx = x - fx;
    const float* p = img + y0 * WW + x0;
    float v00 = p[0], v01 = p[1], v10 = p[WW], v11 = p[WW + 1];
    return v00 * (1.0f - ty) * (1.0f - tx) + v01 * (1.0f - ty) * tx +
           v10 * ty * (1.0f - tx) + v11 * ty * tx;
}

__global__ __launch_bounds__(256) void snake_kernel(const float* __restrict__ node_pos,
                                                    const float* __restrict__ widths) {
    __shared__ float sy[NN], sx[NN], sw[NN], s2y[NN], s2x[NN];
    const int b = blockIdx.x;
    const int i = threadIdx.x;
    const int im1 = max(i - 1, 0), ip1 = min(i + 1, NN - 1);

    sy[i] = node_pos[(b * NN + i) * 2 + 0];
    sx[i] = node_pos[(b * NN + i) * 2 + 1];
    sw[i] = widths[b * NN + i];
    const float* gi0 = g_gimg + (b * 2 + 0) * HH * WW;
    const float* gi1 = g_gimg + (b * 2 + 1) * HH * WW;
    const float* gw = g_gw + b * HH * WW;
    __syncthreads();

    for (int s = 0; s < 50; s++) {
        float pyi = sy[i], pxi = sx[i];
        float fY = bilin(gi0, pyi, pxi);
        float fX = bilin(gi1, pyi, pxi);
        float d2yi = sy[im1] - 2.0f * pyi + sy[ip1];
        float d2xi = sx[im1] - 2.0f * pxi + sx[ip1];
        s2y[i] = d2yi;
        s2x[i] = d2xi;
        __syncthreads();
        float d4y = s2y[im1] - 2.0f * d2yi + s2y[ip1];
        float d4x = s2x[im1] - 2.0f * d2xi + s2x[ip1];
        float npy = pyi + 0.1f * (0.01f * d2yi - 0.005f * d4y + fY);
        float npx = pxi + 0.1f * (0.01f * d2xi - 0.005f * d4x + fX);
        npy = fminf(fmaxf(npy, 0.0f), 255.0f);  // H-1
        npx = fminf(fmaxf(npx, 0.0f), 255.0f);
        // width update: d2(w) from OLD w, force sampled at NEW p (channels pre-summed)
        float wi = sw[i];
        float d2wi = sw[im1] - 2.0f * wi + sw[ip1];
        float fw = bilin(gw, npy, npx);
        float nwi = wi + 0.1f * (0.01f * d2wi + fw);
        nwi = fminf(fmaxf(nwi, 0.0f), 15.0f);  // DMAX
        __syncthreads();
        sy[i] = npy;
        sx[i] = npx;
        sw[i] = nwi;
        __syncthreads();
    }
    g_py[b * NN + i] = sy[i];
    g_px[b * NN + i] = sx[i];
    g_wd[b * NN + i] = sw[i];
}

// ---------------------------------------------------------------------------
// Stage 3: render distance map + fused MSE partial. One block per 32x32 tile.
// Candidate culling: node influences tile only if Linf dist < w + DMAX.
// ---------------------------------------------------------------------------
__global__ __launch_bounds__(256) void render_kernel(const float* __restrict__ pred) {
    __shared__ float cy[NN], cx[NN], cw[NN];
    __shared__ int cnt;
    __shared__ float wsum[8];

    const int b = blockIdx.y;
    const int tile = blockIdx.x;
    const int ty0 = (tile >> 3) * 32, tx0 = (tile & 7) * 32;
    const int t = threadIdx.x;

    if (t == 0) cnt = 0;
    __syncthreads();
    {
        float py = g_py[b * NN + t];
        float px = g_px[b * NN + t];
        float w = g_wd[b * NN + t];
        float m = w + 15.0f;
        if (py >= (float)ty0 - m && py <= (float)(ty0 + 31) + m &&
            px >= (float)tx0 - m && px <= (float)(tx0 + 31) + m) {
            int k = atomicAdd(&cnt, 1);
            cy[k] = py;
            cx[k] = px;
            cw[k] = w;
        }
    }
    __syncthreads();

    const int n = cnt;
    const int tx = t & 31, tyb = t >> 5;  // thread owns rows tyb + {0,8,16,24}
    const float xf = (float)(tx0 + tx);
    float mins[4];
    float yfs[4];
#pragma unroll
    for (int r = 0; r < 4; r++) {
        yfs[r] = (float)(ty0 + tyb + 8 * r);
        mins[r] = 15.0f;  // DMAX: excluded nodes cannot produce < 15 in this tile
    }
    for (int j = 0; j < n; j++) {
        float dx = xf - cx[j];
        float dx2 = dx * dx;
        float pyj = cy[j], wj = cw[j];
#pragma unroll
        for (int r = 0; r < 4; r++) {
            float dy = yfs[r] - pyj;
            float r2 = fmaf(dy, dy, dx2);
            r2 = fmaxf(r2, 1e-18f);
            float d = fmaf(r2, rsqrtf(r2), -wj);  // sqrt(r2) - w
            mins[r] = fminf(mins[r], d);
        }
    }

    float acc = 0.0f;
#pragma unroll
    for (int r = 0; r < 4; r++) {
        float dm = fminf(fmaxf(mins[r], 0.0f), 15.0f);
        int gy = ty0 + tyb + 8 * r, gx = tx0 + tx;
        float e = pred[(b * HH + gy) * WW + gx] - dm;
        acc = fmaf(e, e, acc);
    }
    // Deterministic block reduction.
#pragma unroll
    for (int o = 16; o > 0; o >>= 1) acc += __shfl_xor_sync(0xffffffffu, acc, o);
    if ((t & 31) == 0) wsum[t >> 5] = acc;
    __syncthreads();
    if (t == 0) {
        float s = 0.0f;
#pragma unroll
        for (int k = 0; k < 8; k++) s += wsum[k];
        g_part[b * 64 + tile] = (double)s;
    }
}

// ---------------------------------------------------------------------------
// Stage 4: deterministic final reduction -> scalar mean.
// ---------------------------------------------------------------------------
__global__ __launch_bounds__(256) void reduce_kernel(float* __restrict__ out) {
    __shared__ double s[256];
    const int t = threadIdx.x;
    s[t] = g_part[t];
    __syncthreads();
    for (int o = 128; o > 0; o >>= 1) {
        if (t < o) s[t] += s[t + o];
        __syncthreads();
    }
    if (t == 0) out[0] = (float)(s[0] / (double)(BB * HH * WW));
}

extern "C" void kernel_launch(void* const* d_in, const int* in_sizes, int n_in,
                              void* d_out, int out_size) {
    const float* pred = (const float*)d_in[0];      // (4,1,256,256)
    const float* node_pos = (const float*)d_in[1];  // (4,256,2)
    const float* widths = (const float*)d_in[2];    // (4,256)
    (void)in_sizes; (void)n_in; (void)out_size;

    conv_kernel<<<dim3(8, 8, BB), 256>>>(pred);
    snake_kernel<<<BB, 256>>>(node_pos, widths);
    render_kernel<<<dim3(64, BB), 256>>>(pred);
    reduce_kernel<<<1, 256>>>((float*)d_out);
}

// round 4
// speedup vs baseline: 1.8608x; 1.8608x over previous
#include <cuda_runtime.h>

#define BB 4
#define HH 256
#define WW 256
#define NN 256

// Scratch (static __device__ arrays: allocation-free).
__device__ float2 g_gimg2[BB * HH * WW];  // interleaved (ygrad, xgrad) of pred
__device__ float  g_gw[BB * HH * WW];     // channel-summed grad of |pred|
__device__ int    g_dmap[BB * HH * WW];   // float bits, init 15.0f
__device__ float  g_py[BB * NN], g_px[BB * NN], g_wd[BB * NN];
__device__ double g_part[256];
__device__ unsigned g_ctr = 0;

// ---------------------------------------------------------------------------
// Stage 1: separable 13x13 edge conv, coefficients as FP32 immediates.
// blockIdx.z = b*2 + mode. mode0: signed input -> g_gimg2. mode1: |input| ->
// g_gw (channels summed) + dmap init. One block = 32x32 output tile.
// ---------------------------------------------------------------------------
__global__ __launch_bounds__(256) void conv_kernel(const float* __restrict__ x) {
    // g /= g.sum(); dg = -x/stdev^2 * g, stdev=2, taps at x=-6..6.
    constexpr float KG[13] = {
        0.00221820f, 0.00877313f, 0.02702315f, 0.06482518f, 0.12110938f,
        0.17621311f, 0.19967563f, 0.17621311f, 0.12110938f, 0.06482518f,
        0.02702315f, 0.00877313f, 0.00221820f};
    constexpr float KD[13] = {
        0.00332730f, 0.01096641f, 0.02702315f, 0.04861888f, 0.06055469f,
        0.04405328f, 0.00000000f, -0.04405328f, -0.06055469f, -0.04861888f,
        -0.02702315f, -0.01096641f, -0.00332730f};

    __shared__ float s_in[44][48];
    __shared__ float s_hg[44][32];
    __shared__ float s_hd[44][32];

    const int mode = blockIdx.z & 1;
    const int b = blockIdx.z >> 1;
    const int ty0 = blockIdx.y * 32, tx0 = blockIdx.x * 32;
    const float* xb = x + b * HH * WW;
    const int t = threadIdx.x;

    // Load 44x44 input tile with 6-px halo, zero padding ('SAME'); abs if mode1.
    for (int idx = t; idx < 44 * 44; idx += 256) {
        int iy = idx / 44, ix = idx % 44;
        int gy = ty0 + iy - 6, gx = tx0 + ix - 6;
        float v = 0.0f;
        if ((unsigned)gy < HH && (unsigned)gx < WW) v = xb[gy * WW + gx];
        s_in[iy][ix] = mode ? fabsf(v) : v;
    }
    __syncthreads();

    // Horizontal pass.
    for (int idx = t; idx < 44 * 32; idx += 256) {
        int iy = idx / 32, ix = idx % 32;
        float hg = 0.f, hd = 0.f;
#pragma unroll
        for (int l = 0; l < 13; l++) {
            float v = s_in[iy][ix + l];
            hg = fmaf(v, KG[l], hg);
            hd = fmaf(v, KD[l], hd);
        }
        s_hg[iy][ix] = hg;
        s_hd[iy][ix] = hd;
    }
    __syncthreads();

    // Vertical pass: c0 = dg (x) g row-filtered; c1 = g (x) dg row-filtered.
    for (int idx = t; idx < 32 * 32; idx += 256) {
        int iy = idx / 32, ix = idx % 32;
        float c0 = 0.f, c1 = 0.f;
#pragma unroll
        for (int k = 0; k < 13; k++) {
            c0 = fmaf(s_hg[iy + k][ix], KD[k], c0);
            c1 = fmaf(s_hd[iy + k][ix], KG[k], c1);
        }
        int gy = ty0 + iy, gx = tx0 + ix;
        int o = (b * HH + gy) * WW + gx;
        if (mode == 0) {
            g_gimg2[o] = make_float2(10.0f * c0, 10.0f * c1);  // EXTGRADFAC
        } else {
            g_gw[o] = 10.0f * (c0 + c1);
            g_dmap[o] = 0x41700000;  // 15.0f (DMAX)
        }
    }
}

// ---------------------------------------------------------------------------
// Stage 2: snake optimization. One block per batch, one thread per node.
// Ping-pong state buffers -> single barrier per step.
// ---------------------------------------------------------------------------
__device__ __forceinline__ void bilin_setup(float y, float x, int& off, float& ty, float& tx) {
    y = fminf(fmaxf(y, 0.0f), 254.999f);  // H - 1.001
    x = fminf(fmaxf(x, 0.0f), 254.999f);
    float fy = floorf(y), fx = floorf(x);
    off = (int)fy * WW + (int)fx;
    ty = y - fy;
    tx = x - fx;
}

__global__ __launch_bounds__(256) void snake_kernel(const float* __restrict__ node_pos,
                                                    const float* __restrict__ widths) {
    __shared__ float sy[2][NN], sx[2][NN], sw[2][NN];
    const int b = blockIdx.x;
    const int i = threadIdx.x;
    // Clamped-index compositions for d2 / d4 (5-point, boundary-replicated):
    const int im1 = max(i - 1, 0), ip1 = min(i + 1, NN - 1);
    const int a0 = max(i - 2, 0);
    const int a1 = (i >= 1) ? i : 1;            // min(im1+1, NN-1)
    const int b0 = (i <= NN - 2) ? i : NN - 2;  // max(ip1-1, 0)
    const int b1 = min(i + 2, NN - 1);

    sy[0][i] = node_pos[(b * NN + i) * 2 + 0];
    sx[0][i] = node_pos[(b * NN + i) * 2 + 1];
    sw[0][i] = widths[b * NN + i];
    const float2* gi = g_gimg2 + b * HH * WW;
    const float* gw = g_gw + b * HH * WW;
    __syncthreads();

    int cur = 0;
#pragma unroll 1
    for (int s = 0; s < 50; s++) {
        const float* py = sy[cur];
        const float* px = sx[cur];
        const float* pw = sw[cur];
        float pyi = py[i], pxi = px[i];

        // External force at old position (interleaved channels, LDG.64 x4).
        int off; float ty, tx;
        bilin_setup(pyi, pxi, off, ty, tx);
        float2 v00 = gi[off], v01 = gi[off + 1], v10 = gi[off + WW], v11 = gi[off + WW + 1];
        float w00 = (1.f - ty) * (1.f - tx), w01 = (1.f - ty) * tx;
        float w10 = ty * (1.f - tx), w11 = ty * tx;
        float fY = v00.x * w00 + v01.x * w01 + v10.x * w10 + v11.x * w11;
        float fX = v00.y * w00 + v01.y * w01 + v10.y * w10 + v11.y * w11;

        // d2 and d4 directly from the 5-point clamped stencil.
        float d2ym = py[a0] - 2.f * py[im1] + py[a1];
        float d2yc = py[im1] - 2.f * pyi + py[ip1];
        float d2yp = py[b0] - 2.f * py[ip1] + py[b1];
        float d4y = d2ym - 2.f * d2yc + d2yp;
        float d2xm = px[a0] - 2.f * px[im1] + px[a1];
        float d2xc = px[im1] - 2.f * pxi + px[ip1];
        float d2xp = px[b0] - 2.f * px[ip1] + px[b1];
        float d4x = d2xm - 2.f * d2xc + d2xp;

        float npy = pyi + 0.1f * (0.01f * d2yc - 0.005f * d4y + fY);
        float npx = pxi + 0.1f * (0.01f * d2xc - 0.005f * d4x + fX);
        npy = fminf(fmaxf(npy, 0.0f), 255.0f);
        npx = fminf(fmaxf(npx, 0.0f), 255.0f);

        // Width: d2 from OLD widths, force at NEW position (channels pre-summed).
        float wi = pw[i];
        float d2w = pw[im1] - 2.f * wi + pw[ip1];
        int off2; float ty2, tx2;
        bilin_setup(npy, npx, off2, ty2, tx2);
        float u00 = gw[off2], u01 = gw[off2 + 1], u10 = gw[off2 + WW], u11 = gw[off2 + WW + 1];
        float fw = u00 * (1.f - ty2) * (1.f - tx2) + u01 * (1.f - ty2) * tx2 +
                   u10 * ty2 * (1.f - tx2) + u11 * ty2 * tx2;
        float nwi = wi + 0.1f * (0.01f * d2w + fw);
        nwi = fminf(fmaxf(nwi, 0.0f), 15.0f);

        int nxt = cur ^ 1;
        sy[nxt][i] = npy;
        sx[nxt][i] = npx;
        sw[nxt][i] = nwi;
        __syncthreads();
        cur = nxt;
    }
    g_py[b * NN + i] = sy[cur][i];
    g_px[b * NN + i] = sx[cur][i];
    g_wd[b * NN + i] = sw[cur][i];
}

// ---------------------------------------------------------------------------
// Stage 3: scatter render. One block per (node, batch): rasterize the node's
// influence disk (radius w+DMAX <= 30) with atomicMin on float bits.
// atomicMin is order-independent -> deterministic.
// ---------------------------------------------------------------------------
__global__ __launch_bounds__(256) void scatter_kernel() {
    const int j = blockIdx.x;
    const int b = blockIdx.y;
    const float py = g_py[b * NN + j];
    const float px = g_px[b * NN + j];
    const float w = g_wd[b * NN + j];
    const float R = w + 15.0f;
    const float R2 = R * R;

    int y0 = max((int)ceilf(py - R), 0);
    int y1 = min((int)floorf(py + R), HH - 1);
    int x0 = max((int)ceilf(px - R), 0);
    int x1 = min((int)floorf(px + R), WW - 1);

    const int c = threadIdx.x & 63;   // column within box (width <= 61)
    const int rb = threadIdx.x >> 6;  // 4 row phases
    const int xg = x0 + c;
    if (xg > x1) return;

    const float dx = (float)xg - px;
    const float dx2 = dx * dx;
    int* dmap = g_dmap + b * HH * WW;

    for (int y = y0 + rb; y <= y1; y += 4) {
        float dy = (float)y - py;
        float r2 = fmaf(dy, dy, dx2);
        if (r2 < R2) {
            r2 = fmaxf(r2, 1e-18f);
            float d = fmaf(r2, rsqrtf(r2), -w);  // sqrt(r2) - w, in (-w, 15)
            d = fmaxf(d, 0.0f);                  // clip low; high bound by r2<R2
            atomicMin(&dmap[y * WW + xg], __float_as_int(d));
        }
    }
}

// ---------------------------------------------------------------------------
// Stage 4: fused MSE + deterministic final reduction (last-block pattern).
// ---------------------------------------------------------------------------
__global__ __launch_bounds__(256) void mse_kernel(const float* __restrict__ pred,
                                                  float* __restrict__ out) {
    __shared__ float wsum[8];
    const int t = threadIdx.x;
    const int base = (blockIdx.x * 256 + t) * 4;  // 256 blocks x 256 thr x 4 px

    float4 p = *(const float4*)(pred + base);
    int4 dm = *(const int4*)(g_dmap + base);
    float e0 = p.x - __int_as_float(dm.x);
    float e1 = p.y - __int_as_float(dm.y);
    float e2 = p.z - __int_as_float(dm.z);
    float e3 = p.w - __int_as_float(dm.w);
    float acc = fmaf(e0, e0, fmaf(e1, e1, fmaf(e2, e2, e3 * e3)));

#pragma unroll
    for (int o = 16; o > 0; o >>= 1) acc += __shfl_xor_sync(0xffffffffu, acc, o);
    if ((t & 31) == 0) wsum[t >> 5] = acc;
    __syncthreads();
    if (t == 0) {
        float s = 0.0f;
#pragma unroll
        for (int k = 0; k < 8; k++) s += wsum[k];
        g_part[blockIdx.x] = (double)s;
    }
    // Last-block final reduction (fixed-order -> deterministic).
    __shared__ double sd[256];
    __shared__ unsigned is_last;
    __threadfence();
    if (t == 0) is_last = (atomicAdd(&g_ctr, 1u) == 255u);
    __syncthreads();
    if (!is_last) return;
    __threadfence();
    sd[t] = g_part[t];
    __syncthreads();
    for (int o = 128; o > 0; o >>= 1) {
        if (t < o) sd[t] += sd[t + o];
        __syncthreads();
    }
    if (t == 0) {
        out[0] = (float)(sd[0] / (double)(BB * HH * WW));
        g_ctr = 0;  // reset for next graph replay
    }
}

extern "C" void kernel_launch(void* const* d_in, const int* in_sizes, int n_in,
                              void* d_out, int out_size) {
    const float* pred = (const float*)d_in[0];      // (4,1,256,256)
    const float* node_pos = (const float*)d_in[1];  // (4,256,2)
    const float* widths = (const float*)d_in[2];    // (4,256)
    (void)in_sizes; (void)n_in; (void)out_size;

    conv_kernel<<<dim3(8, 8, BB * 2), 256>>>(pred);
    snake_kernel<<<BB, 256>>>(node_pos, widths);
    scatter_kernel<<<dim3(NN, BB), 256>>>();
    mse_kernel<<<256, 256>>>(pred, (float*)d_out);
}